// round 15
// baseline (speedup 1.0000x reference)
#include <cuda_runtime.h>
#include <cuda_bf16.h>
#include <math.h>
#include <stdint.h>

// ---------------- problem constants ----------------
constexpr int B_  = 4;
constexpr int T_  = 2048;
constexpr int S_  = 1024;
constexpr int C_  = 1024;
constexpr int E_  = 512;
constexpr int D_  = 64;

constexpr int MQ = B_ * T_;   // 8192
constexpr int ME = B_ * S_;   // 4096
constexpr int MH = MQ / 2;    // 4096 decoder rows per batch half
constexpr int MB = MQ / 4;    // 2048 decoder rows per batch (quarter)
constexpr int EH = ME / 2;    // 2048 encoder rows per batch half

// ---------------- scratch ----------------
__device__ float g_tmp[ME * C_];                       // pre-LN fp32

__device__ __nv_bfloat16 g_xh[MQ * C_],  g_xl[MQ * C_];
__device__ __nv_bfloat16 g_eh[ME * E_],  g_el[ME * E_];
__device__ __nv_bfloat16 g_hh[ME * C_],  g_hl[ME * C_];
__device__ __nv_bfloat16 g_ench[ME * C_],g_encl[ME * C_];
__device__ __nv_bfloat16 g_qh[MQ * C_],  g_ql[MQ * C_];
__device__ __nv_bfloat16 g_kh[ME * C_],  g_kl[ME * C_];
__device__ __nv_bfloat16 g_vh[ME * C_],  g_vl[ME * C_];
__device__ __nv_bfloat16 g_yh[MQ * C_],  g_yl[MQ * C_];
__device__ __nv_bfloat16 g_w1h[C_ * E_], g_w1l[C_ * E_];
__device__ __nv_bfloat16 g_w2h[C_ * C_], g_w2l[C_ * C_];
__device__ __nv_bfloat16 g_wqh[C_ * C_], g_wql[C_ * C_];
__device__ __nv_bfloat16 g_wkh[C_ * C_], g_wkl[C_ * C_];
__device__ __nv_bfloat16 g_wvh[C_ * C_], g_wvl[C_ * C_];
__device__ __nv_bfloat16 g_wph[C_ * C_], g_wpl[C_ * C_];

// ---------------- streams/events (load-time init, never destroyed) ---------
struct GraphResources {
    cudaStream_t s1, s2;
    cudaEvent_t  eS, eW, eT12, eQA, eQB, eKVB, eA0, eA1, eA2, ePA;
    GraphResources() {
        cudaStreamCreateWithFlags(&s1, cudaStreamNonBlocking);
        cudaStreamCreateWithFlags(&s2, cudaStreamNonBlocking);
        cudaEventCreateWithFlags(&eS,   cudaEventDisableTiming);
        cudaEventCreateWithFlags(&eW,   cudaEventDisableTiming);
        cudaEventCreateWithFlags(&eT12, cudaEventDisableTiming);
        cudaEventCreateWithFlags(&eQA,  cudaEventDisableTiming);
        cudaEventCreateWithFlags(&eQB,  cudaEventDisableTiming);
        cudaEventCreateWithFlags(&eKVB, cudaEventDisableTiming);
        cudaEventCreateWithFlags(&eA0,  cudaEventDisableTiming);
        cudaEventCreateWithFlags(&eA1,  cudaEventDisableTiming);
        cudaEventCreateWithFlags(&eA2,  cudaEventDisableTiming);
        cudaEventCreateWithFlags(&ePA,  cudaEventDisableTiming);
    }
};
static GraphResources g_res;

// ---------------- helpers ----------------
__device__ __forceinline__ uint32_t smem_u32(const void* p) {
    uint32_t a;
    asm("{ .reg .u64 t; cvta.to.shared.u64 t, %1; cvt.u32.u64 %0, t; }" : "=r"(a) : "l"(p));
    return a;
}
__device__ __forceinline__ void ldmx4(uint32_t* r, uint32_t addr) {
    asm volatile("ldmatrix.sync.aligned.m8n8.x4.shared.b16 {%0,%1,%2,%3}, [%4];"
                 : "=r"(r[0]), "=r"(r[1]), "=r"(r[2]), "=r"(r[3]) : "r"(addr));
}
__device__ __forceinline__ void ldmx4t(uint32_t* r, uint32_t addr) {
    asm volatile("ldmatrix.sync.aligned.m8n8.x4.trans.shared.b16 {%0,%1,%2,%3}, [%4];"
                 : "=r"(r[0]), "=r"(r[1]), "=r"(r[2]), "=r"(r[3]) : "r"(addr));
}
__device__ __forceinline__ void cp16(uint32_t dst, const void* src) {
    asm volatile("cp.async.cg.shared.global [%0], [%1], 16;" :: "r"(dst), "l"(src));
}
__device__ __forceinline__ void cp_commit() {
    asm volatile("cp.async.commit_group;" ::: "memory");
}
template<int N> __device__ __forceinline__ void cp_wait() {
    asm volatile("cp.async.wait_group %0;" :: "n"(N) : "memory");
}

#define MMA_BF16(acc, a, b0, b1)                                              \
    asm volatile(                                                             \
        "mma.sync.aligned.m16n8k16.row.col.f32.bf16.bf16.f32 "                \
        "{%0,%1,%2,%3},{%4,%5,%6,%7},{%8,%9},{%0,%1,%2,%3};"                  \
        : "+f"((acc)[0]), "+f"((acc)[1]), "+f"((acc)[2]), "+f"((acc)[3])      \
        : "r"((a)[0]), "r"((a)[1]), "r"((a)[2]), "r"((a)[3]),                 \
          "r"(b0), "r"(b1))

__device__ __forceinline__ float gelu_f(float x) {
    return 0.5f * x * (1.f + erff(x * 0.70710678118654752f));
}

// rounding split (prepass / epilogues)
__device__ __forceinline__ void split2(float a, float b, uint32_t& h, uint32_t& l) {
    __nv_bfloat16 ha = __float2bfloat16(a), hb = __float2bfloat16(b);
    __nv_bfloat162 hp = __halves2bfloat162(ha, hb);
    __nv_bfloat162 lp = __floats2bfloat162_rn(a - __bfloat162float(ha),
                                              b - __bfloat162float(hb));
    h = *reinterpret_cast<uint32_t*>(&hp);
    l = *reinterpret_cast<uint32_t*>(&lp);
}

// truncation split via byte_perm (hot attention repack)
__device__ __forceinline__ void split2t(float a, float b, uint32_t& h, uint32_t& l) {
    const uint32_t ua = __float_as_uint(a), ub = __float_as_uint(b);
    h = __byte_perm(ua, ub, 0x7632);
    const float la = a - __uint_as_float(ua & 0xFFFF0000u);
    const float lb = b - __uint_as_float(ub & 0xFFFF0000u);
    l = __byte_perm(__float_as_uint(la), __float_as_uint(lb), 0x7632);
}

// ---------------- elementwise split: fp32 -> hi/lo bf16 --------------------
__global__ __launch_bounds__(256)
void split_act(const float* __restrict__ in, __nv_bfloat16* __restrict__ oh,
               __nv_bfloat16* __restrict__ ol)
{
    const size_t i = (size_t)blockIdx.x * 256 + threadIdx.x;
    float4 v = ((const float4*)in)[i];
    uint32_t h0, l0, h1, l1;
    split2(v.x, v.y, h0, l0);
    split2(v.z, v.w, h1, l1);
    ((uint2*)oh)[i] = make_uint2(h0, h1);
    ((uint2*)ol)[i] = make_uint2(l0, l1);
}

// ---------------- transpose + split: W[R,Cc] -> Wt hi/lo [Cc,R] ------------
__global__ __launch_bounds__(256)
void transpose_split(const float* __restrict__ in,
                     __nv_bfloat16* __restrict__ oh, __nv_bfloat16* __restrict__ ol,
                     int R, int Cc)
{
    __shared__ float t[32][33];
    const int bx = blockIdx.x * 32, by = blockIdx.y * 32;
    const int tx = threadIdx.x & 31, tyq = threadIdx.x >> 5;
    #pragma unroll
    for (int i = tyq; i < 32; i += 8)
        t[i][tx] = in[(size_t)(by + i) * Cc + bx + tx];
    __syncthreads();
    #pragma unroll
    for (int i = tyq; i < 32; i += 8) {
        float v = t[tx][i];
        __nv_bfloat16 h = __float2bfloat16(v);
        oh[(size_t)(bx + i) * R + by + tx] = h;
        ol[(size_t)(bx + i) * R + by + tx] = __float2bfloat16(v - __bfloat162float(h));
    }
}

// ---------------- GEMM: C = A[M,K] @ Bt[N,K]^T (hi/lo bf16, cp.async) ------
constexpr uint32_t G_TILE  = 128 * 64;
constexpr uint32_t G_STAGE = 4 * G_TILE;       // 32768
constexpr uint32_t G_SMEM  = 3 * G_STAGE;      // 98304

__global__ __launch_bounds__(256, 2)
void gemm_cp(const __nv_bfloat16* __restrict__ Ah, const __nv_bfloat16* __restrict__ Al,
             const __nv_bfloat16* __restrict__ Bh, const __nv_bfloat16* __restrict__ Bl,
             const float* __restrict__ bias,
             float* __restrict__ outF,
             __nv_bfloat16* __restrict__ outH, __nv_bfloat16* __restrict__ outL,
             int M, int N, int K, int act, float scale)
{
    extern __shared__ char smem[];
    const uint32_t sb = smem_u32(smem);
    const int tid  = threadIdx.x;
    const int lane = tid & 31;
    const int wid  = tid >> 5;
    const int wm   = wid & 3;
    const int wn   = wid >> 2;
    const int m0   = blockIdx.y * 128;
    const int n0   = blockIdx.x * 128;
    const int NC   = K >> 5;

    float acc[2][8][4];
    #pragma unroll
    for (int i = 0; i < 2; i++)
        #pragma unroll
        for (int j = 0; j < 8; j++)
            #pragma unroll
            for (int t = 0; t < 4; t++) acc[i][j][t] = 0.f;

    auto issue = [&](int c) {
        const uint32_t st = sb + (uint32_t)(c % 3) * G_STAGE;
        #pragma unroll
        for (int j = 0; j < 8; j++) {
            const int g   = tid + 256 * j;
            const int arr = g >> 9;
            const int rem = g & 511;
            const int row = rem >> 2;
            const int seg = rem & 3;
            const __nv_bfloat16* src =
                (arr == 0) ? Ah : (arr == 1) ? Al : (arr == 2) ? Bh : Bl;
            const int base = (arr < 2) ? m0 : n0;
            src += (size_t)(base + row) * K + c * 32 + seg * 8;
            const uint32_t dst = st + (uint32_t)arr * G_TILE + row * 64 +
                                 (((uint32_t)(seg ^ ((row >> 1) & 3))) << 4);
            cp16(dst, src);
        }
    };

    issue(0); cp_commit();
    issue(1); cp_commit();

    const uint32_t arow = lane & 15;
    const uint32_t nrow = (lane & 7) | ((lane >> 4) << 3);

    for (int c = 0; c < NC; c++) {
        cp_wait<1>();
        __syncthreads();

        if (c + 2 < NC) issue(c + 2);
        cp_commit();

        const uint32_t st = sb + (uint32_t)(c % 3) * G_STAGE;

        #pragma unroll
        for (int kb = 0; kb < 2; kb++) {
            uint32_t ah[2][4], al[2][4];
            const uint32_t sA = kb * 2 + (lane >> 4);
            #pragma unroll
            for (int mi = 0; mi < 2; mi++) {
                const uint32_t r = wm * 32 + arow + mi * 16;
                const uint32_t addr = st + r * 64 + ((sA ^ ((r >> 1) & 3)) << 4);
                ldmx4(ah[mi], addr);
                ldmx4(al[mi], addr + G_TILE);
            }
            const uint32_t sB = kb * 2 + ((lane >> 3) & 1);
            #pragma unroll
            for (int np = 0; np < 4; np++) {
                const uint32_t r = wn * 64 + np * 16 + nrow;
                const uint32_t addr = st + 2 * G_TILE + r * 64 + ((sB ^ ((r >> 1) & 3)) << 4);
                uint32_t bh[4], bl[4];
                ldmx4(bh, addr);
                ldmx4(bl, addr + G_TILE);
                #pragma unroll
                for (int mi = 0; mi < 2; mi++)
                    #pragma unroll
                    for (int t = 0; t < 2; t++)
                        MMA_BF16(acc[mi][np * 2 + t], ah[mi], bh[2 * t], bh[2 * t + 1]);
                #pragma unroll
                for (int mi = 0; mi < 2; mi++)
                    #pragma unroll
                    for (int t = 0; t < 2; t++)
                        MMA_BF16(acc[mi][np * 2 + t], ah[mi], bl[2 * t], bl[2 * t + 1]);
                #pragma unroll
                for (int mi = 0; mi < 2; mi++)
                    #pragma unroll
                    for (int t = 0; t < 2; t++)
                        MMA_BF16(acc[mi][np * 2 + t], al[mi], bh[2 * t], bh[2 * t + 1]);
            }
        }
    }

    // epilogue
    const int rbase = m0 + wm * 32 + (lane >> 2);
    const int cbase = n0 + wn * 64 + (lane & 3) * 2;
    #pragma unroll
    for (int mi = 0; mi < 2; mi++) {
        #pragma unroll
        for (int ni = 0; ni < 8; ni++) {
            const int col = cbase + ni * 8;
            const float bx = bias[col], by = bias[col + 1];
            const int r1 = rbase + mi * 16;
            float v0x = acc[mi][ni][0] + bx, v0y = acc[mi][ni][1] + by;
            float v1x = acc[mi][ni][2] + bx, v1y = acc[mi][ni][3] + by;
            if (act == 1) {
                v0x = gelu_f(v0x); v0y = gelu_f(v0y);
                v1x = gelu_f(v1x); v1y = gelu_f(v1y);
            }
            v0x *= scale; v0y *= scale; v1x *= scale; v1y *= scale;
            if (outF) {
                *(float2*)(outF + (size_t)r1 * N + col)       = make_float2(v0x, v0y);
                *(float2*)(outF + (size_t)(r1 + 8) * N + col) = make_float2(v1x, v1y);
            }
            if (outH) {
                uint32_t h0, l0, h1, l1;
                split2(v0x, v0y, h0, l0);
                split2(v1x, v1y, h1, l1);
                ((uint32_t*)outH)[((size_t)r1 * N + col) >> 1]       = h0;
                ((uint32_t*)outL)[((size_t)r1 * N + col) >> 1]       = l0;
                ((uint32_t*)outH)[((size_t)(r1 + 8) * N + col) >> 1] = h1;
                ((uint32_t*)outL)[((size_t)(r1 + 8) * N + col) >> 1] = l1;
            }
        }
    }
}

// ---------------- LayerNorm + split ----------------------------------------
__global__ __launch_bounds__(256)
void ln_split(const float* __restrict__ in, const float* __restrict__ g,
              const float* __restrict__ b,
              __nv_bfloat16* __restrict__ oh, __nv_bfloat16* __restrict__ ol)
{
    const int row = blockIdx.x;
    const int tid = threadIdx.x;
    float4 v = ((const float4*)(in + (size_t)row * C_))[tid];

    float s  = v.x + v.y + v.z + v.w;
    float s2 = v.x * v.x + v.y * v.y + v.z * v.z + v.w * v.w;
    #pragma unroll
    for (int off = 16; off > 0; off >>= 1) {
        s  += __shfl_xor_sync(0xffffffffu, s,  off);
        s2 += __shfl_xor_sync(0xffffffffu, s2, off);
    }
    __shared__ float sh[16];
    const int w = tid >> 5;
    if ((tid & 31) == 0) { sh[w] = s; sh[w + 8] = s2; }
    __syncthreads();
    if (tid < 32) {
        float a  = (tid < 8) ? sh[tid]     : 0.f;
        float a2 = (tid < 8) ? sh[tid + 8] : 0.f;
        #pragma unroll
        for (int off = 4; off > 0; off >>= 1) {
            a  += __shfl_xor_sync(0xffffffffu, a,  off);
            a2 += __shfl_xor_sync(0xffffffffu, a2, off);
        }
        if (tid == 0) { sh[0] = a; sh[1] = a2; }
    }
    __syncthreads();
    const float mu   = sh[0] * (1.f / C_);
    const float var  = sh[1] * (1.f / C_) - mu * mu;
    const float rstd = rsqrtf(var + 1e-5f);

    float4 gg = ((const float4*)g)[tid];
    float4 bb = ((const float4*)b)[tid];
    float ox = (v.x - mu) * rstd * gg.x + bb.x;
    float oy = (v.y - mu) * rstd * gg.y + bb.y;
    float oz = (v.z - mu) * rstd * gg.z + bb.z;
    float ow = (v.w - mu) * rstd * gg.w + bb.w;
    uint32_t h0, l0, h1, l1;
    split2(ox, oy, h0, l0);
    split2(oz, ow, h1, l1);
    const size_t base = ((size_t)row * C_) >> 1;
    ((uint32_t*)oh)[base + tid * 2]     = h0;
    ((uint32_t*)ol)[base + tid * 2]     = l0;
    ((uint32_t*)oh)[base + tid * 2 + 1] = h1;
    ((uint32_t*)ol)[base + tid * 2 + 1] = l1;
}

// ---------------- Tensor-core flash attention (batch-offset) ----------------
constexpr uint32_t A_QT    = 16384;
constexpr uint32_t A_KVT   = 8192;
constexpr uint32_t A_KV0   = 2 * A_QT;            // 32768
constexpr uint32_t A_KVST  = 4 * A_KVT;           // 32768
constexpr uint32_t A_MSK   = A_KV0 + 2 * A_KVST;  // 98304
constexpr uint32_t A_SMEM  = A_MSK + 2 * 64 * 4;  // 98816

__global__ __launch_bounds__(256, 2)
void attn_tc(const __nv_bfloat16* __restrict__ qh, const __nv_bfloat16* __restrict__ ql,
             const __nv_bfloat16* __restrict__ kh, const __nv_bfloat16* __restrict__ kl,
             const __nv_bfloat16* __restrict__ vh, const __nv_bfloat16* __restrict__ vl,
             const int* __restrict__ mask,
             __nv_bfloat16* __restrict__ yh, __nv_bfloat16* __restrict__ yl,
             int bOff)
{
    extern __shared__ char smem[];
    const uint32_t sb = smem_u32(smem);
    float* mskp = (float*)(smem + A_MSK);

    const int b   = blockIdx.z + bOff;
    const int h   = blockIdx.y;
    const int t0  = blockIdx.x * 128;
    const int tid = threadIdx.x;
    const int lane = tid & 31;
    const int wid  = tid >> 5;

    const size_t qrow0 = (size_t)(b * T_ + t0);
    const size_t krow0 = (size_t)(b * S_);
    const int*   mb    = mask + b * S_;

    auto issueQ = [&]() {
        #pragma unroll
        for (int j = 0; j < 8; j++) {
            const int g   = tid + 256 * j;
            const int arr = g >> 10;
            const int rem = g & 1023;
            const int row = rem >> 3;
            const int seg = rem & 7;
            const __nv_bfloat16* src = (arr ? ql : qh) +
                (qrow0 + row) * C_ + h * D_ + seg * 8;
            const uint32_t dst = sb + (uint32_t)arr * A_QT + row * 128 +
                                 (((uint32_t)(seg ^ (row & 7))) << 4);
            cp16(dst, src);
        }
    };
    auto issueKV = [&](int c) {
        const uint32_t st = sb + A_KV0 + (uint32_t)(c & 1) * A_KVST;
        const int s0 = c * 64;
        #pragma unroll
        for (int j = 0; j < 8; j++) {
            const int g   = tid + 256 * j;
            const int arr = g >> 9;
            const int rem = g & 511;
            const int row = rem >> 3;
            const int seg = rem & 7;
            const __nv_bfloat16* src =
                ((arr == 0) ? kh : (arr == 1) ? kl : (arr == 2) ? vh : vl) +
                (krow0 + s0 + row) * C_ + h * D_ + seg * 8;
            const uint32_t dst = st + (uint32_t)arr * A_KVT + row * 128 +
                                 (((uint32_t)(seg ^ (row & 7))) << 4);
            cp16(dst, src);
        }
        if (tid < 64)
            mskp[(c & 1) * 64 + tid] = mb[s0 + tid] ? 0.f : -1e30f;
    };

    issueQ(); issueKV(0); cp_commit();
    issueKV(1); cp_commit();

    float oacc[8][4];
    #pragma unroll
    for (int i = 0; i < 8; i++)
        #pragma unroll
        for (int t = 0; t < 4; t++) oacc[i][t] = 0.f;
    float m0r = -INFINITY, m1r = -INFINITY, l0r = 0.f, l1r = 0.f;

    const uint32_t nrow = (lane & 7) | ((lane >> 4) << 3);
    const uint32_t qr   = wid * 16 + (lane & 15);

    for (int c = 0; c < 16; c++) {
        cp_wait<1>();
        __syncthreads();

        const uint32_t st = sb + A_KV0 + (uint32_t)(c & 1) * A_KVST;
        const float* msks = mskp + (c & 1) * 64;

        // ---- scores = Q K^T (3-pass) ----
        float sc[8][4];
        #pragma unroll
        for (int i = 0; i < 8; i++)
            #pragma unroll
            for (int t = 0; t < 4; t++) sc[i][t] = 0.f;

        #pragma unroll
        for (int kc = 0; kc < 4; kc++) {
            uint32_t qfh[4], qfl[4];
            const uint32_t sQ = kc * 2 + (lane >> 4);
            const uint32_t qaddr = sb + qr * 128 + ((sQ ^ (qr & 7)) << 4);
            ldmx4(qfh, qaddr);
            ldmx4(qfl, qaddr + A_QT);

            const uint32_t sB = kc * 2 + ((lane >> 3) & 1);
            #pragma unroll
            for (int npp = 0; npp < 2; npp++) {
                uint32_t bh4[2][4], bl4[2][4];
                #pragma unroll
                for (int u = 0; u < 2; u++) {
                    const uint32_t r = (npp * 2 + u) * 16 + nrow;
                    const uint32_t addr = st + r * 128 + ((sB ^ (r & 7)) << 4);
                    ldmx4(bh4[u], addr);
                    ldmx4(bl4[u], addr + A_KVT);
                }
                #pragma unroll
                for (int u = 0; u < 2; u++)
                    #pragma unroll
                    for (int t = 0; t < 2; t++)
                        MMA_BF16(sc[(npp * 2 + u) * 2 + t], qfh, bh4[u][2 * t], bh4[u][2 * t + 1]);
                #pragma unroll
                for (int u = 0; u < 2; u++)
                    #pragma unroll
                    for (int t = 0; t < 2; t++)
                        MMA_BF16(sc[(npp * 2 + u) * 2 + t], qfh, bl4[u][2 * t], bl4[u][2 * t + 1]);
                #pragma unroll
                for (int u = 0; u < 2; u++)
                    #pragma unroll
                    for (int t = 0; t < 2; t++)
                        MMA_BF16(sc[(npp * 2 + u) * 2 + t], qfl, bh4[u][2 * t], bh4[u][2 * t + 1]);
            }
        }

        // ---- mask + online softmax (base-2; l kept as per-thread partial) ----
        const int cq = (lane & 3) * 2;
        float tmax0 = -INFINITY, tmax1 = -INFINITY;
        #pragma unroll
        for (int nb = 0; nb < 8; nb++) {
            const float ma = msks[nb * 8 + cq];
            const float mbv = msks[nb * 8 + cq + 1];
            sc[nb][0] += ma;  sc[nb][1] += mbv;
            sc[nb][2] += ma;  sc[nb][3] += mbv;
            tmax0 = fmaxf(tmax0, fmaxf(sc[nb][0], sc[nb][1]));
            tmax1 = fmaxf(tmax1, fmaxf(sc[nb][2], sc[nb][3]));
        }
        tmax0 = fmaxf(tmax0, __shfl_xor_sync(0xffffffffu, tmax0, 1));
        tmax0 = fmaxf(tmax0, __shfl_xor_sync(0xffffffffu, tmax0, 2));
        tmax1 = fmaxf(tmax1, __shfl_xor_sync(0xffffffffu, tmax1, 1));
        tmax1 = fmaxf(tmax1, __shfl_xor_sync(0xffffffffu, tmax1, 2));

        const float mn0 = fmaxf(m0r, tmax0);
        const float mn1 = fmaxf(m1r, tmax1);
        const float al0 = exp2f(m0r - mn0);
        const float al1 = exp2f(m1r - mn1);
        m0r = mn0; m1r = mn1;

        float sum0 = 0.f, sum1 = 0.f;
        #pragma unroll
        for (int nb = 0; nb < 8; nb++) {
            sc[nb][0] = exp2f(sc[nb][0] - mn0);
            sc[nb][1] = exp2f(sc[nb][1] - mn0);
            sc[nb][2] = exp2f(sc[nb][2] - mn1);
            sc[nb][3] = exp2f(sc[nb][3] - mn1);
            sum0 += sc[nb][0] + sc[nb][1];
            sum1 += sc[nb][2] + sc[nb][3];
        }
        // per-thread partial l (alphas row-consistent; reduce once at the end)
        l0r = l0r * al0 + sum0;
        l1r = l1r * al1 + sum1;

        if (__ballot_sync(0xffffffffu, (al0 < 1.f) | (al1 < 1.f))) {
            #pragma unroll
            for (int nd = 0; nd < 8; nd++) {
                oacc[nd][0] *= al0; oacc[nd][1] *= al0;
                oacc[nd][2] *= al1; oacc[nd][3] *= al1;
            }
        }

        // ---- O += P V (3-pass, byte_perm truncation repack) ----
        #pragma unroll
        for (int kc = 0; kc < 4; kc++) {
            uint32_t pah[4], pal[4];
            split2t(sc[2 * kc][0],     sc[2 * kc][1],     pah[0], pal[0]);
            split2t(sc[2 * kc][2],     sc[2 * kc][3],     pah[1], pal[1]);
            split2t(sc[2 * kc + 1][0], sc[2 * kc + 1][1], pah[2], pal[2]);
            split2t(sc[2 * kc + 1][2], sc[2 * kc + 1][3], pah[3], pal[3]);

            const uint32_t rV = kc * 16 + (lane & 15);
            #pragma unroll
            for (int np = 0; np < 4; np++) {
                const uint32_t sV = np * 2 + (lane >> 4);
                const uint32_t addr = st + 2 * A_KVT + rV * 128 + ((sV ^ (rV & 7)) << 4);
                uint32_t vh4[4], vl4[4];
                ldmx4t(vh4, addr);
                ldmx4t(vl4, addr + A_KVT);
                #pragma unroll
                for (int t = 0; t < 2; t++)
                    MMA_BF16(oacc[np * 2 + t], pah, vh4[2 * t], vh4[2 * t + 1]);
                #pragma unroll
                for (int t = 0; t < 2; t++)
                    MMA_BF16(oacc[np * 2 + t], pah, vl4[2 * t], vl4[2 * t + 1]);
                #pragma unroll
                for (int t = 0; t < 2; t++)
                    MMA_BF16(oacc[np * 2 + t], pal, vh4[2 * t], vh4[2 * t + 1]);
            }
        }

        __syncthreads();
        if (c + 2 < 16) issueKV(c + 2);
        cp_commit();
    }

    // ---- final l reduction (deferred from loop) ----
    l0r += __shfl_xor_sync(0xffffffffu, l0r, 1);
    l0r += __shfl_xor_sync(0xffffffffu, l0r, 2);
    l1r += __shfl_xor_sync(0xffffffffu, l1r, 1);
    l1r += __shfl_xor_sync(0xffffffffu, l1r, 2);

    // ---- epilogue ----
    const float inv0 = 1.f / l0r;
    const float inv1 = 1.f / l1r;
    const size_t row0 = qrow0 + wid * 16 + (lane >> 2);
    const size_t row1 = row0 + 8;
    #pragma unroll
    for (int nd = 0; nd < 8; nd++) {
        const int col = h * D_ + nd * 8 + (lane & 3) * 2;
        uint32_t h0, l0, h1, l1;
        split2(oacc[nd][0] * inv0, oacc[nd][1] * inv0, h0, l0);
        split2(oacc[nd][2] * inv1, oacc[nd][3] * inv1, h1, l1);
        ((uint32_t*)yh)[(row0 * C_ + col) >> 1] = h0;
        ((uint32_t*)yl)[(row0 * C_ + col) >> 1] = l0;
        ((uint32_t*)yh)[(row1 * C_ + col) >> 1] = h1;
        ((uint32_t*)yl)[(row1 * C_ + col) >> 1] = l1;
    }
}

// ---------------- launcher: quarter-pipelined tail DAG ----------------------
extern "C" void kernel_launch(void* const* d_in, const int* in_sizes, int n_in,
                              void* d_out, int out_size)
{
    const float* x    = (const float*)d_in[0];
    const float* eemb = (const float*)d_in[1];
    const int*   emsk = (const int*)  d_in[2];
    const float* W1   = (const float*)d_in[3];
    const float* b1   = (const float*)d_in[4];
    const float* W2   = (const float*)d_in[5];
    const float* b2   = (const float*)d_in[6];
    const float* lng  = (const float*)d_in[7];
    const float* lnb  = (const float*)d_in[8];
    const float* Wq   = (const float*)d_in[9];
    const float* bq   = (const float*)d_in[10];
    const float* Wk   = (const float*)d_in[11];
    const float* bk   = (const float*)d_in[12];
    const float* Wv   = (const float*)d_in[13];
    const float* bv   = (const float*)d_in[14];
    const float* Wp   = (const float*)d_in[15];
    const float* bp   = (const float*)d_in[16];
    float* out = (float*)d_out;

    float* tmp;
    cudaGetSymbolAddress((void**)&tmp, g_tmp);
    __nv_bfloat16 *xh,*xl,*eh,*el,*hh,*hl,*ench,*encl,*qh,*ql,*kh,*kl,*vh,*vl,*yh,*yl;
    __nv_bfloat16 *w1h,*w1l,*w2h,*w2l,*wqh,*wql,*wkh,*wkl,*wvh,*wvl,*wph,*wpl;
    cudaGetSymbolAddress((void**)&xh, g_xh);   cudaGetSymbolAddress((void**)&xl, g_xl);
    cudaGetSymbolAddress((void**)&eh, g_eh);   cudaGetSymbolAddress((void**)&el, g_el);
    cudaGetSymbolAddress((void**)&hh, g_hh);   cudaGetSymbolAddress((void**)&hl, g_hl);
    cudaGetSymbolAddress((void**)&ench, g_ench); cudaGetSymbolAddress((void**)&encl, g_encl);
    cudaGetSymbolAddress((void**)&qh, g_qh);   cudaGetSymbolAddress((void**)&ql, g_ql);
    cudaGetSymbolAddress((void**)&kh, g_kh);   cudaGetSymbolAddress((void**)&kl, g_kl);
    cudaGetSymbolAddress((void**)&vh, g_vh);   cudaGetSymbolAddress((void**)&vl, g_vl);
    cudaGetSymbolAddress((void**)&yh, g_yh);   cudaGetSymbolAddress((void**)&yl, g_yl);
    cudaGetSymbolAddress((void**)&w1h, g_w1h); cudaGetSymbolAddress((void**)&w1l, g_w1l);
    cudaGetSymbolAddress((void**)&w2h, g_w2h); cudaGetSymbolAddress((void**)&w2l, g_w2l);
    cudaGetSymbolAddress((void**)&wqh, g_wqh); cudaGetSymbolAddress((void**)&wql, g_wql);
    cudaGetSymbolAddress((void**)&wkh, g_wkh); cudaGetSymbolAddress((void**)&wkl, g_wkl);
    cudaGetSymbolAddress((void**)&wvh, g_wvh); cudaGetSymbolAddress((void**)&wvl, g_wvl);
    cudaGetSymbolAddress((void**)&wph, g_wph); cudaGetSymbolAddress((void**)&wpl, g_wpl);

    cudaFuncSetAttribute(gemm_cp, cudaFuncAttributeMaxDynamicSharedMemorySize, G_SMEM);
    cudaFuncSetAttribute(attn_tc, cudaFuncAttributeMaxDynamicSharedMemorySize, A_SMEM);

    cudaStream_t s1 = g_res.s1, s2 = g_res.s2;
    const size_t EHC = (size_t)EH * C_;   // encoder half offset (C cols)
    const size_t EHE = (size_t)EH * E_;   // encoder half offset (E cols)
    const size_t MHC = (size_t)MH * C_;   // decoder half offset
    const size_t MBC = (size_t)MB * C_;   // decoder quarter offset

    // ---- fork ----
    cudaEventRecord(g_res.eS, 0);
    cudaStreamWaitEvent(s1, g_res.eS, 0);
    cudaStreamWaitEvent(s2, g_res.eS, 0);

    // s1: decoder Q chain (batch halves)
    split_act<<<MQ * C_ / 1024, 256, 0, s1>>>(x, xh, xl);
    transpose_split<<<dim3(C_ / 32, C_ / 32), 256, 0, s1>>>(Wq, wqh, wql, C_, C_);
    gemm_cp<<<dim3(C_ / 128, MH / 128), 256, G_SMEM, s1>>>(
        xh, xl, wqh, wql, bq, nullptr, qh, ql, MH, C_, C_, 0, 0.1803368801111f);
    cudaEventRecord(g_res.eQA, s1);
    gemm_cp<<<dim3(C_ / 128, MH / 128), 256, G_SMEM, s1>>>(
        xh + MHC, xl + MHC, wqh, wql, bq, nullptr,
        qh + MHC, ql + MHC, MH, C_, C_, 0, 0.1803368801111f);
    cudaEventRecord(g_res.eQB, s1);

    // main: encoder half A chain
    split_act<<<ME * E_ / 1024, 256>>>(eemb, eh, el);
    transpose_split<<<dim3(C_ / 32, E_ / 32), 256>>>(W1, w1h, w1l, E_, C_);
    transpose_split<<<dim3(C_ / 32, C_ / 32), 256>>>(W2, w2h, w2l, C_, C_);
    cudaEventRecord(g_res.eT12, 0);
    gemm_cp<<<dim3(C_ / 128, EH / 128), 256, G_SMEM>>>(
        eh, el, w1h, w1l, b1, nullptr, hh, hl, EH, C_, E_, 1, 1.f);
    gemm_cp<<<dim3(C_ / 128, EH / 128), 256, G_SMEM>>>(
        hh, hl, w2h, w2l, b2, tmp, nullptr, nullptr, EH, C_, C_, 0, 1.f);
    ln_split<<<EH, 256>>>(tmp, lng, lnb, ench, encl);

    // s2: K/V/P transposes, then encoder half B chain + its K/V projections
    transpose_split<<<dim3(C_ / 32, C_ / 32), 256, 0, s2>>>(Wk, wkh, wkl, C_, C_);
    transpose_split<<<dim3(C_ / 32, C_ / 32), 256, 0, s2>>>(Wv, wvh, wvl, C_, C_);
    transpose_split<<<dim3(C_ / 32, C_ / 32), 256, 0, s2>>>(Wp, wph, wpl, C_, C_);
    cudaEventRecord(g_res.eW, s2);
    cudaStreamWaitEvent(s2, g_res.eT12, 0);
    gemm_cp<<<dim3(C_ / 128, EH / 128), 256, G_SMEM, s2>>>(
        eh + EHE, el + EHE, w1h, w1l, b1, nullptr, hh + EHC, hl + EHC, EH, C_, E_, 1, 1.f);
    gemm_cp<<<dim3(C_ / 128, EH / 128), 256, G_SMEM, s2>>>(
        hh + EHC, hl + EHC, w2h, w2l, b2, tmp + EHC, nullptr, nullptr, EH, C_, C_, 0, 1.f);
    ln_split<<<EH, 256, 0, s2>>>(tmp + EHC, lng, lnb, ench + EHC, encl + EHC);
    gemm_cp<<<dim3(C_ / 128, EH / 128), 256, G_SMEM, s2>>>(
        ench + EHC, encl + EHC, wkh, wkl, bk, nullptr, kh + EHC, kl + EHC, EH, C_, C_, 0, 1.f);
    gemm_cp<<<dim3(C_ / 128, EH / 128), 256, G_SMEM, s2>>>(
        ench + EHC, encl + EHC, wvh, wvl, bv, nullptr, vh + EHC, vl + EHC, EH, C_, C_, 0, 1.f);
    cudaEventRecord(g_res.eKVB, s2);

    // main: K/V projections for half A, then attention quarters b0, b1
    cudaStreamWaitEvent(0, g_res.eW, 0);
    gemm_cp<<<dim3(C_ / 128, EH / 128), 256, G_SMEM>>>(
        ench, encl, wkh, wkl, bk, nullptr, kh, kl, EH, C_, C_, 0, 1.f);
    gemm_cp<<<dim3(C_ / 128, EH / 128), 256, G_SMEM>>>(
        ench, encl, wvh, wvl, bv, nullptr, vh, vl, EH, C_, C_, 0, 1.f);
    cudaStreamWaitEvent(0, g_res.eQA, 0);
    attn_tc<<<dim3(T_ / 128, 16, 1), 256, A_SMEM>>>(
        qh, ql, kh, kl, vh, vl, emsk, yh, yl, 0);
    cudaEventRecord(g_res.eA0, 0);
    attn_tc<<<dim3(T_ / 128, 16, 1), 256, A_SMEM>>>(
        qh, ql, kh, kl, vh, vl, emsk, yh, yl, 1);
    cudaEventRecord(g_res.eA1, 0);

    // s1: pproj b0 ∥ attn b1, pproj b1 ∥ attn b2
    cudaStreamWaitEvent(s1, g_res.eA0, 0);
    gemm_cp<<<dim3(C_ / 128, MB / 128), 256, G_SMEM, s1>>>(
        yh, yl, wph, wpl, bp, out, nullptr, nullptr, MB, C_, C_, 0, 1.f);
    cudaStreamWaitEvent(s1, g_res.eA1, 0);
    gemm_cp<<<dim3(C_ / 128, MB / 128), 256, G_SMEM, s1>>>(
        yh + MBC, yl + MBC, wph, wpl, bp, out + MBC, nullptr, nullptr,
        MB, C_, C_, 0, 1.f);

    // main: attention quarters b2, b3 (need qB and kvB)
    cudaStreamWaitEvent(0, g_res.eQB, 0);
    cudaStreamWaitEvent(0, g_res.eKVB, 0);
    attn_tc<<<dim3(T_ / 128, 16, 1), 256, A_SMEM>>>(
        qh, ql, kh, kl, vh, vl, emsk, yh, yl, 2);
    cudaEventRecord(g_res.eA2, 0);
    attn_tc<<<dim3(T_ / 128, 16, 1), 256, A_SMEM>>>(
        qh, ql, kh, kl, vh, vl, emsk, yh, yl, 3);

    // s1: pproj b2 ∥ attn b3
    cudaStreamWaitEvent(s1, g_res.eA2, 0);
    gemm_cp<<<dim3(C_ / 128, MB / 128), 256, G_SMEM, s1>>>(
        yh + 2 * MBC, yl + 2 * MBC, wph, wpl, bp, out + 2 * MBC, nullptr, nullptr,
        MB, C_, C_, 0, 1.f);
    cudaEventRecord(g_res.ePA, s1);

    // main: pproj b3, join
    gemm_cp<<<dim3(C_ / 128, MB / 128), 256, G_SMEM>>>(
        yh + 3 * MBC, yl + 3 * MBC, wph, wpl, bp, out + 3 * MBC, nullptr, nullptr,
        MB, C_, C_, 0, 1.f);
    cudaStreamWaitEvent(0, g_res.ePA, 0);
}

// round 16
// speedup vs baseline: 1.0796x; 1.0796x over previous
#include <cuda_runtime.h>
#include <cuda_bf16.h>
#include <math.h>
#include <stdint.h>

// ---------------- problem constants ----------------
constexpr int B_  = 4;
constexpr int T_  = 2048;
constexpr int S_  = 1024;
constexpr int C_  = 1024;
constexpr int E_  = 512;
constexpr int D_  = 64;

constexpr int MQ = B_ * T_;   // 8192
constexpr int ME = B_ * S_;   // 4096
constexpr int MH = MQ / 2;    // 4096 decoder rows per batch half
constexpr int EH = ME / 2;    // 2048 encoder rows per batch half

// ---------------- scratch ----------------
__device__ float g_tmp[ME * C_];                       // pre-LN fp32

__device__ __nv_bfloat16 g_xh[MQ * C_],  g_xl[MQ * C_];
__device__ __nv_bfloat16 g_eh[ME * E_],  g_el[ME * E_];
__device__ __nv_bfloat16 g_hh[ME * C_],  g_hl[ME * C_];
__device__ __nv_bfloat16 g_ench[ME * C_],g_encl[ME * C_];
__device__ __nv_bfloat16 g_qh[MQ * C_],  g_ql[MQ * C_];
__device__ __nv_bfloat16 g_kh[ME * C_],  g_kl[ME * C_];
__device__ __nv_bfloat16 g_vh[ME * C_],  g_vl[ME * C_];
__device__ __nv_bfloat16 g_yh[MQ * C_],  g_yl[MQ * C_];
__device__ __nv_bfloat16 g_w1h[C_ * E_], g_w1l[C_ * E_];
__device__ __nv_bfloat16 g_w2h[C_ * C_], g_w2l[C_ * C_];
__device__ __nv_bfloat16 g_wqh[C_ * C_], g_wql[C_ * C_];
__device__ __nv_bfloat16 g_wkh[C_ * C_], g_wkl[C_ * C_];
__device__ __nv_bfloat16 g_wvh[C_ * C_], g_wvl[C_ * C_];
__device__ __nv_bfloat16 g_wph[C_ * C_], g_wpl[C_ * C_];

// ---------------- streams/events (load-time init, never destroyed) ---------
struct GraphResources {
    cudaStream_t s1, s2;
    cudaEvent_t  eS, eW, eT12, eQA, eQB, eKVB, eAA, ePA;
    GraphResources() {
        cudaStreamCreateWithFlags(&s1, cudaStreamNonBlocking);
        cudaStreamCreateWithFlags(&s2, cudaStreamNonBlocking);
        cudaEventCreateWithFlags(&eS,   cudaEventDisableTiming);
        cudaEventCreateWithFlags(&eW,   cudaEventDisableTiming);
        cudaEventCreateWithFlags(&eT12, cudaEventDisableTiming);
        cudaEventCreateWithFlags(&eQA,  cudaEventDisableTiming);
        cudaEventCreateWithFlags(&eQB,  cudaEventDisableTiming);
        cudaEventCreateWithFlags(&eKVB, cudaEventDisableTiming);
        cudaEventCreateWithFlags(&eAA,  cudaEventDisableTiming);
        cudaEventCreateWithFlags(&ePA,  cudaEventDisableTiming);
    }
};
static GraphResources g_res;

// ---------------- helpers ----------------
__device__ __forceinline__ uint32_t smem_u32(const void* p) {
    uint32_t a;
    asm("{ .reg .u64 t; cvta.to.shared.u64 t, %1; cvt.u32.u64 %0, t; }" : "=r"(a) : "l"(p));
    return a;
}
__device__ __forceinline__ void ldmx4(uint32_t* r, uint32_t addr) {
    asm volatile("ldmatrix.sync.aligned.m8n8.x4.shared.b16 {%0,%1,%2,%3}, [%4];"
                 : "=r"(r[0]), "=r"(r[1]), "=r"(r[2]), "=r"(r[3]) : "r"(addr));
}
__device__ __forceinline__ void ldmx4t(uint32_t* r, uint32_t addr) {
    asm volatile("ldmatrix.sync.aligned.m8n8.x4.trans.shared.b16 {%0,%1,%2,%3}, [%4];"
                 : "=r"(r[0]), "=r"(r[1]), "=r"(r[2]), "=r"(r[3]) : "r"(addr));
}
__device__ __forceinline__ void cp16(uint32_t dst, const void* src) {
    asm volatile("cp.async.cg.shared.global [%0], [%1], 16;" :: "r"(dst), "l"(src));
}
__device__ __forceinline__ void cp_commit() {
    asm volatile("cp.async.commit_group;" ::: "memory");
}
template<int N> __device__ __forceinline__ void cp_wait() {
    asm volatile("cp.async.wait_group %0;" :: "n"(N) : "memory");
}

#define MMA_BF16(acc, a, b0, b1)                                              \
    asm volatile(                                                             \
        "mma.sync.aligned.m16n8k16.row.col.f32.bf16.bf16.f32 "                \
        "{%0,%1,%2,%3},{%4,%5,%6,%7},{%8,%9},{%0,%1,%2,%3};"                  \
        : "+f"((acc)[0]), "+f"((acc)[1]), "+f"((acc)[2]), "+f"((acc)[3])      \
        : "r"((a)[0]), "r"((a)[1]), "r"((a)[2]), "r"((a)[3]),                 \
          "r"(b0), "r"(b1))

__device__ __forceinline__ float gelu_f(float x) {
    return 0.5f * x * (1.f + erff(x * 0.70710678118654752f));
}

// rounding split (prepass / epilogues)
__device__ __forceinline__ void split2(float a, float b, uint32_t& h, uint32_t& l) {
    __nv_bfloat16 ha = __float2bfloat16(a), hb = __float2bfloat16(b);
    __nv_bfloat162 hp = __halves2bfloat162(ha, hb);
    __nv_bfloat162 lp = __floats2bfloat162_rn(a - __bfloat162float(ha),
                                              b - __bfloat162float(hb));
    h = *reinterpret_cast<uint32_t*>(&hp);
    l = *reinterpret_cast<uint32_t*>(&lp);
}

// truncation split via byte_perm (hot attention repack)
__device__ __forceinline__ void split2t(float a, float b, uint32_t& h, uint32_t& l) {
    const uint32_t ua = __float_as_uint(a), ub = __float_as_uint(b);
    h = __byte_perm(ua, ub, 0x7632);
    const float la = a - __uint_as_float(ua & 0xFFFF0000u);
    const float lb = b - __uint_as_float(ub & 0xFFFF0000u);
    l = __byte_perm(__float_as_uint(la), __float_as_uint(lb), 0x7632);
}

// ---------------- elementwise split: fp32 -> hi/lo bf16 --------------------
__global__ __launch_bounds__(256)
void split_act(const float* __restrict__ in, __nv_bfloat16* __restrict__ oh,
               __nv_bfloat16* __restrict__ ol)
{
    const size_t i = (size_t)blockIdx.x * 256 + threadIdx.x;
    float4 v = ((const float4*)in)[i];
    uint32_t h0, l0, h1, l1;
    split2(v.x, v.y, h0, l0);
    split2(v.z, v.w, h1, l1);
    ((uint2*)oh)[i] = make_uint2(h0, h1);
    ((uint2*)ol)[i] = make_uint2(l0, l1);
}

// ---------------- transpose + split: W[R,Cc] -> Wt hi/lo [Cc,R] ------------
__global__ __launch_bounds__(256)
void transpose_split(const float* __restrict__ in,
                     __nv_bfloat16* __restrict__ oh, __nv_bfloat16* __restrict__ ol,
                     int R, int Cc)
{
    __shared__ float t[32][33];
    const int bx = blockIdx.x * 32, by = blockIdx.y * 32;
    const int tx = threadIdx.x & 31, tyq = threadIdx.x >> 5;
    #pragma unroll
    for (int i = tyq; i < 32; i += 8)
        t[i][tx] = in[(size_t)(by + i) * Cc + bx + tx];
    __syncthreads();
    #pragma unroll
    for (int i = tyq; i < 32; i += 8) {
        float v = t[tx][i];
        __nv_bfloat16 h = __float2bfloat16(v);
        oh[(size_t)(bx + i) * R + by + tx] = h;
        ol[(size_t)(bx + i) * R + by + tx] = __float2bfloat16(v - __bfloat162float(h));
    }
}

// ---------------- GEMM: C = A[M,K] @ Bt[N,K]^T (hi/lo bf16, cp.async) ------
constexpr uint32_t G_TILE  = 128 * 64;
constexpr uint32_t G_STAGE = 4 * G_TILE;       // 32768
constexpr uint32_t G_SMEM  = 3 * G_STAGE;      // 98304

__global__ __launch_bounds__(256, 2)
void gemm_cp(const __nv_bfloat16* __restrict__ Ah, const __nv_bfloat16* __restrict__ Al,
             const __nv_bfloat16* __restrict__ Bh, const __nv_bfloat16* __restrict__ Bl,
             const float* __restrict__ bias,
             float* __restrict__ outF,
             __nv_bfloat16* __restrict__ outH, __nv_bfloat16* __restrict__ outL,
             int M, int N, int K, int act, float scale)
{
    extern __shared__ char smem[];
    const uint32_t sb = smem_u32(smem);
    const int tid  = threadIdx.x;
    const int lane = tid & 31;
    const int wid  = tid >> 5;
    const int wm   = wid & 3;
    const int wn   = wid >> 2;
    const int m0   = blockIdx.y * 128;
    const int n0   = blockIdx.x * 128;
    const int NC   = K >> 5;

    float acc[2][8][4];
    #pragma unroll
    for (int i = 0; i < 2; i++)
        #pragma unroll
        for (int j = 0; j < 8; j++)
            #pragma unroll
            for (int t = 0; t < 4; t++) acc[i][j][t] = 0.f;

    auto issue = [&](int c) {
        const uint32_t st = sb + (uint32_t)(c % 3) * G_STAGE;
        #pragma unroll
        for (int j = 0; j < 8; j++) {
            const int g   = tid + 256 * j;
            const int arr = g >> 9;
            const int rem = g & 511;
            const int row = rem >> 2;
            const int seg = rem & 3;
            const __nv_bfloat16* src =
                (arr == 0) ? Ah : (arr == 1) ? Al : (arr == 2) ? Bh : Bl;
            const int base = (arr < 2) ? m0 : n0;
            src += (size_t)(base + row) * K + c * 32 + seg * 8;
            const uint32_t dst = st + (uint32_t)arr * G_TILE + row * 64 +
                                 (((uint32_t)(seg ^ ((row >> 1) & 3))) << 4);
            cp16(dst, src);
        }
    };

    issue(0); cp_commit();
    issue(1); cp_commit();

    const uint32_t arow = lane & 15;
    const uint32_t nrow = (lane & 7) | ((lane >> 4) << 3);

    for (int c = 0; c < NC; c++) {
        cp_wait<1>();
        __syncthreads();

        if (c + 2 < NC) issue(c + 2);
        cp_commit();

        const uint32_t st = sb + (uint32_t)(c % 3) * G_STAGE;

        #pragma unroll
        for (int kb = 0; kb < 2; kb++) {
            uint32_t ah[2][4], al[2][4];
            const uint32_t sA = kb * 2 + (lane >> 4);
            #pragma unroll
            for (int mi = 0; mi < 2; mi++) {
                const uint32_t r = wm * 32 + arow + mi * 16;
                const uint32_t addr = st + r * 64 + ((sA ^ ((r >> 1) & 3)) << 4);
                ldmx4(ah[mi], addr);
                ldmx4(al[mi], addr + G_TILE);
            }
            const uint32_t sB = kb * 2 + ((lane >> 3) & 1);
            #pragma unroll
            for (int np = 0; np < 4; np++) {
                const uint32_t r = wn * 64 + np * 16 + nrow;
                const uint32_t addr = st + 2 * G_TILE + r * 64 + ((sB ^ ((r >> 1) & 3)) << 4);
                uint32_t bh[4], bl[4];
                ldmx4(bh, addr);
                ldmx4(bl, addr + G_TILE);
                #pragma unroll
                for (int mi = 0; mi < 2; mi++)
                    #pragma unroll
                    for (int t = 0; t < 2; t++)
                        MMA_BF16(acc[mi][np * 2 + t], ah[mi], bh[2 * t], bh[2 * t + 1]);
                #pragma unroll
                for (int mi = 0; mi < 2; mi++)
                    #pragma unroll
                    for (int t = 0; t < 2; t++)
                        MMA_BF16(acc[mi][np * 2 + t], ah[mi], bl[2 * t], bl[2 * t + 1]);
                #pragma unroll
                for (int mi = 0; mi < 2; mi++)
                    #pragma unroll
                    for (int t = 0; t < 2; t++)
                        MMA_BF16(acc[mi][np * 2 + t], al[mi], bh[2 * t], bh[2 * t + 1]);
            }
        }
    }

    // epilogue
    const int rbase = m0 + wm * 32 + (lane >> 2);
    const int cbase = n0 + wn * 64 + (lane & 3) * 2;
    #pragma unroll
    for (int mi = 0; mi < 2; mi++) {
        #pragma unroll
        for (int ni = 0; ni < 8; ni++) {
            const int col = cbase + ni * 8;
            const float bx = bias[col], by = bias[col + 1];
            const int r1 = rbase + mi * 16;
            float v0x = acc[mi][ni][0] + bx, v0y = acc[mi][ni][1] + by;
            float v1x = acc[mi][ni][2] + bx, v1y = acc[mi][ni][3] + by;
            if (act == 1) {
                v0x = gelu_f(v0x); v0y = gelu_f(v0y);
                v1x = gelu_f(v1x); v1y = gelu_f(v1y);
            }
            v0x *= scale; v0y *= scale; v1x *= scale; v1y *= scale;
            if (outF) {
                *(float2*)(outF + (size_t)r1 * N + col)       = make_float2(v0x, v0y);
                *(float2*)(outF + (size_t)(r1 + 8) * N + col) = make_float2(v1x, v1y);
            }
            if (outH) {
                uint32_t h0, l0, h1, l1;
                split2(v0x, v0y, h0, l0);
                split2(v1x, v1y, h1, l1);
                ((uint32_t*)outH)[((size_t)r1 * N + col) >> 1]       = h0;
                ((uint32_t*)outL)[((size_t)r1 * N + col) >> 1]       = l0;
                ((uint32_t*)outH)[((size_t)(r1 + 8) * N + col) >> 1] = h1;
                ((uint32_t*)outL)[((size_t)(r1 + 8) * N + col) >> 1] = l1;
            }
        }
    }
}

// ---------------- LayerNorm + split ----------------------------------------
__global__ __launch_bounds__(256)
void ln_split(const float* __restrict__ in, const float* __restrict__ g,
              const float* __restrict__ b,
              __nv_bfloat16* __restrict__ oh, __nv_bfloat16* __restrict__ ol)
{
    const int row = blockIdx.x;
    const int tid = threadIdx.x;
    float4 v = ((const float4*)(in + (size_t)row * C_))[tid];

    float s  = v.x + v.y + v.z + v.w;
    float s2 = v.x * v.x + v.y * v.y + v.z * v.z + v.w * v.w;
    #pragma unroll
    for (int off = 16; off > 0; off >>= 1) {
        s  += __shfl_xor_sync(0xffffffffu, s,  off);
        s2 += __shfl_xor_sync(0xffffffffu, s2, off);
    }
    __shared__ float sh[16];
    const int w = tid >> 5;
    if ((tid & 31) == 0) { sh[w] = s; sh[w + 8] = s2; }
    __syncthreads();
    if (tid < 32) {
        float a  = (tid < 8) ? sh[tid]     : 0.f;
        float a2 = (tid < 8) ? sh[tid + 8] : 0.f;
        #pragma unroll
        for (int off = 4; off > 0; off >>= 1) {
            a  += __shfl_xor_sync(0xffffffffu, a,  off);
            a2 += __shfl_xor_sync(0xffffffffu, a2, off);
        }
        if (tid == 0) { sh[0] = a; sh[1] = a2; }
    }
    __syncthreads();
    const float mu   = sh[0] * (1.f / C_);
    const float var  = sh[1] * (1.f / C_) - mu * mu;
    const float rstd = rsqrtf(var + 1e-5f);

    float4 gg = ((const float4*)g)[tid];
    float4 bb = ((const float4*)b)[tid];
    float ox = (v.x - mu) * rstd * gg.x + bb.x;
    float oy = (v.y - mu) * rstd * gg.y + bb.y;
    float oz = (v.z - mu) * rstd * gg.z + bb.z;
    float ow = (v.w - mu) * rstd * gg.w + bb.w;
    uint32_t h0, l0, h1, l1;
    split2(ox, oy, h0, l0);
    split2(oz, ow, h1, l1);
    const size_t base = ((size_t)row * C_) >> 1;
    ((uint32_t*)oh)[base + tid * 2]     = h0;
    ((uint32_t*)ol)[base + tid * 2]     = l0;
    ((uint32_t*)oh)[base + tid * 2 + 1] = h1;
    ((uint32_t*)ol)[base + tid * 2 + 1] = l1;
}

// ---------------- Tensor-core flash attention (batch-offset) ----------------
constexpr uint32_t A_QT    = 16384;
constexpr uint32_t A_KVT   = 8192;
constexpr uint32_t A_KV0   = 2 * A_QT;            // 32768
constexpr uint32_t A_KVST  = 4 * A_KVT;           // 32768
constexpr uint32_t A_MSK   = A_KV0 + 2 * A_KVST;  // 98304
constexpr uint32_t A_SMEM  = A_MSK + 2 * 64 * 4;  // 98816

__global__ __launch_bounds__(256, 2)
void attn_tc(const __nv_bfloat16* __restrict__ qh, const __nv_bfloat16* __restrict__ ql,
             const __nv_bfloat16* __restrict__ kh, const __nv_bfloat16* __restrict__ kl,
             const __nv_bfloat16* __restrict__ vh, const __nv_bfloat16* __restrict__ vl,
             const int* __restrict__ mask,
             __nv_bfloat16* __restrict__ yh, __nv_bfloat16* __restrict__ yl,
             int bOff)
{
    extern __shared__ char smem[];
    const uint32_t sb = smem_u32(smem);
    float* mskp = (float*)(smem + A_MSK);

    const int b   = blockIdx.z + bOff;
    const int h   = blockIdx.y;
    const int t0  = blockIdx.x * 128;
    const int tid = threadIdx.x;
    const int lane = tid & 31;
    const int wid  = tid >> 5;

    const size_t qrow0 = (size_t)(b * T_ + t0);
    const size_t krow0 = (size_t)(b * S_);
    const int*   mb    = mask + b * S_;

    auto issueQ = [&]() {
        #pragma unroll
        for (int j = 0; j < 8; j++) {
            const int g   = tid + 256 * j;
            const int arr = g >> 10;
            const int rem = g & 1023;
            const int row = rem >> 3;
            const int seg = rem & 7;
            const __nv_bfloat16* src = (arr ? ql : qh) +
                (qrow0 + row) * C_ + h * D_ + seg * 8;
            const uint32_t dst = sb + (uint32_t)arr * A_QT + row * 128 +
                                 (((uint32_t)(seg ^ (row & 7))) << 4);
            cp16(dst, src);
        }
    };
    auto issueKV = [&](int c) {
        const uint32_t st = sb + A_KV0 + (uint32_t)(c & 1) * A_KVST;
        const int s0 = c * 64;
        #pragma unroll
        for (int j = 0; j < 8; j++) {
            const int g   = tid + 256 * j;
            const int arr = g >> 9;
            const int rem = g & 511;
            const int row = rem >> 3;
            const int seg = rem & 7;
            const __nv_bfloat16* src =
                ((arr == 0) ? kh : (arr == 1) ? kl : (arr == 2) ? vh : vl) +
                (krow0 + s0 + row) * C_ + h * D_ + seg * 8;
            const uint32_t dst = st + (uint32_t)arr * A_KVT + row * 128 +
                                 (((uint32_t)(seg ^ (row & 7))) << 4);
            cp16(dst, src);
        }
        if (tid < 64)
            mskp[(c & 1) * 64 + tid] = mb[s0 + tid] ? 0.f : -1e30f;
    };

    issueQ(); issueKV(0); cp_commit();
    issueKV(1); cp_commit();

    float oacc[8][4];
    #pragma unroll
    for (int i = 0; i < 8; i++)
        #pragma unroll
        for (int t = 0; t < 4; t++) oacc[i][t] = 0.f;
    float m0r = -INFINITY, m1r = -INFINITY, l0r = 0.f, l1r = 0.f;

    const uint32_t nrow = (lane & 7) | ((lane >> 4) << 3);
    const uint32_t qr   = wid * 16 + (lane & 15);

    for (int c = 0; c < 16; c++) {
        cp_wait<1>();
        __syncthreads();

        const uint32_t st = sb + A_KV0 + (uint32_t)(c & 1) * A_KVST;
        const float* msks = mskp + (c & 1) * 64;

        // ---- scores = Q K^T (3-pass) ----
        float sc[8][4];
        #pragma unroll
        for (int i = 0; i < 8; i++)
            #pragma unroll
            for (int t = 0; t < 4; t++) sc[i][t] = 0.f;

        #pragma unroll
        for (int kc = 0; kc < 4; kc++) {
            uint32_t qfh[4], qfl[4];
            const uint32_t sQ = kc * 2 + (lane >> 4);
            const uint32_t qaddr = sb + qr * 128 + ((sQ ^ (qr & 7)) << 4);
            ldmx4(qfh, qaddr);
            ldmx4(qfl, qaddr + A_QT);

            const uint32_t sB = kc * 2 + ((lane >> 3) & 1);
            #pragma unroll
            for (int npp = 0; npp < 2; npp++) {
                uint32_t bh4[2][4], bl4[2][4];
                #pragma unroll
                for (int u = 0; u < 2; u++) {
                    const uint32_t r = (npp * 2 + u) * 16 + nrow;
                    const uint32_t addr = st + r * 128 + ((sB ^ (r & 7)) << 4);
                    ldmx4(bh4[u], addr);
                    ldmx4(bl4[u], addr + A_KVT);
                }
                #pragma unroll
                for (int u = 0; u < 2; u++)
                    #pragma unroll
                    for (int t = 0; t < 2; t++)
                        MMA_BF16(sc[(npp * 2 + u) * 2 + t], qfh, bh4[u][2 * t], bh4[u][2 * t + 1]);
                #pragma unroll
                for (int u = 0; u < 2; u++)
                    #pragma unroll
                    for (int t = 0; t < 2; t++)
                        MMA_BF16(sc[(npp * 2 + u) * 2 + t], qfh, bl4[u][2 * t], bl4[u][2 * t + 1]);
                #pragma unroll
                for (int u = 0; u < 2; u++)
                    #pragma unroll
                    for (int t = 0; t < 2; t++)
                        MMA_BF16(sc[(npp * 2 + u) * 2 + t], qfl, bh4[u][2 * t], bh4[u][2 * t + 1]);
            }
        }

        // ---- mask + online softmax (base-2; l kept as per-thread partial) ----
        const int cq = (lane & 3) * 2;
        float tmax0 = -INFINITY, tmax1 = -INFINITY;
        #pragma unroll
        for (int nb = 0; nb < 8; nb++) {
            const float ma = msks[nb * 8 + cq];
            const float mbv = msks[nb * 8 + cq + 1];
            sc[nb][0] += ma;  sc[nb][1] += mbv;
            sc[nb][2] += ma;  sc[nb][3] += mbv;
            tmax0 = fmaxf(tmax0, fmaxf(sc[nb][0], sc[nb][1]));
            tmax1 = fmaxf(tmax1, fmaxf(sc[nb][2], sc[nb][3]));
        }
        tmax0 = fmaxf(tmax0, __shfl_xor_sync(0xffffffffu, tmax0, 1));
        tmax0 = fmaxf(tmax0, __shfl_xor_sync(0xffffffffu, tmax0, 2));
        tmax1 = fmaxf(tmax1, __shfl_xor_sync(0xffffffffu, tmax1, 1));
        tmax1 = fmaxf(tmax1, __shfl_xor_sync(0xffffffffu, tmax1, 2));

        const float mn0 = fmaxf(m0r, tmax0);
        const float mn1 = fmaxf(m1r, tmax1);
        const float al0 = exp2f(m0r - mn0);
        const float al1 = exp2f(m1r - mn1);
        m0r = mn0; m1r = mn1;

        float sum0 = 0.f, sum1 = 0.f;
        #pragma unroll
        for (int nb = 0; nb < 8; nb++) {
            sc[nb][0] = exp2f(sc[nb][0] - mn0);
            sc[nb][1] = exp2f(sc[nb][1] - mn0);
            sc[nb][2] = exp2f(sc[nb][2] - mn1);
            sc[nb][3] = exp2f(sc[nb][3] - mn1);
            sum0 += sc[nb][0] + sc[nb][1];
            sum1 += sc[nb][2] + sc[nb][3];
        }
        // per-thread partial l (alphas row-consistent; reduce once at the end)
        l0r = l0r * al0 + sum0;
        l1r = l1r * al1 + sum1;

        if (__ballot_sync(0xffffffffu, (al0 < 1.f) | (al1 < 1.f))) {
            #pragma unroll
            for (int nd = 0; nd < 8; nd++) {
                oacc[nd][0] *= al0; oacc[nd][1] *= al0;
                oacc[nd][2] *= al1; oacc[nd][3] *= al1;
            }
        }

        // ---- O += P V (3-pass, byte_perm truncation repack) ----
        #pragma unroll
        for (int kc = 0; kc < 4; kc++) {
            uint32_t pah[4], pal[4];
            split2t(sc[2 * kc][0],     sc[2 * kc][1],     pah[0], pal[0]);
            split2t(sc[2 * kc][2],     sc[2 * kc][3],     pah[1], pal[1]);
            split2t(sc[2 * kc + 1][0], sc[2 * kc + 1][1], pah[2], pal[2]);
            split2t(sc[2 * kc + 1][2], sc[2 * kc + 1][3], pah[3], pal[3]);

            const uint32_t rV = kc * 16 + (lane & 15);
            #pragma unroll
            for (int np = 0; np < 4; np++) {
                const uint32_t sV = np * 2 + (lane >> 4);
                const uint32_t addr = st + 2 * A_KVT + rV * 128 + ((sV ^ (rV & 7)) << 4);
                uint32_t vh4[4], vl4[4];
                ldmx4t(vh4, addr);
                ldmx4t(vl4, addr + A_KVT);
                #pragma unroll
                for (int t = 0; t < 2; t++)
                    MMA_BF16(oacc[np * 2 + t], pah, vh4[2 * t], vh4[2 * t + 1]);
                #pragma unroll
                for (int t = 0; t < 2; t++)
                    MMA_BF16(oacc[np * 2 + t], pah, vl4[2 * t], vl4[2 * t + 1]);
                #pragma unroll
                for (int t = 0; t < 2; t++)
                    MMA_BF16(oacc[np * 2 + t], pal, vh4[2 * t], vh4[2 * t + 1]);
            }
        }

        __syncthreads();
        if (c + 2 < 16) issueKV(c + 2);
        cp_commit();
    }

    // ---- final l reduction (deferred from loop) ----
    l0r += __shfl_xor_sync(0xffffffffu, l0r, 1);
    l0r += __shfl_xor_sync(0xffffffffu, l0r, 2);
    l1r += __shfl_xor_sync(0xffffffffu, l1r, 1);
    l1r += __shfl_xor_sync(0xffffffffu, l1r, 2);

    // ---- epilogue ----
    const float inv0 = 1.f / l0r;
    const float inv1 = 1.f / l1r;
    const size_t row0 = qrow0 + wid * 16 + (lane >> 2);
    const size_t row1 = row0 + 8;
    #pragma unroll
    for (int nd = 0; nd < 8; nd++) {
        const int col = h * D_ + nd * 8 + (lane & 3) * 2;
        uint32_t h0, l0, h1, l1;
        split2(oacc[nd][0] * inv0, oacc[nd][1] * inv0, h0, l0);
        split2(oacc[nd][2] * inv1, oacc[nd][3] * inv1, h1, l1);
        ((uint32_t*)yh)[(row0 * C_ + col) >> 1] = h0;
        ((uint32_t*)yl)[(row0 * C_ + col) >> 1] = l0;
        ((uint32_t*)yh)[(row1 * C_ + col) >> 1] = h1;
        ((uint32_t*)yl)[(row1 * C_ + col) >> 1] = l1;
    }
}

// ---------------- launcher: deep batch-half pipelined DAG -------------------
extern "C" void kernel_launch(void* const* d_in, const int* in_sizes, int n_in,
                              void* d_out, int out_size)
{
    const float* x    = (const float*)d_in[0];
    const float* eemb = (const float*)d_in[1];
    const int*   emsk = (const int*)  d_in[2];
    const float* W1   = (const float*)d_in[3];
    const float* b1   = (const float*)d_in[4];
    const float* W2   = (const float*)d_in[5];
    const float* b2   = (const float*)d_in[6];
    const float* lng  = (const float*)d_in[7];
    const float* lnb  = (const float*)d_in[8];
    const float* Wq   = (const float*)d_in[9];
    const float* bq   = (const float*)d_in[10];
    const float* Wk   = (const float*)d_in[11];
    const float* bk   = (const float*)d_in[12];
    const float* Wv   = (const float*)d_in[13];
    const float* bv   = (const float*)d_in[14];
    const float* Wp   = (const float*)d_in[15];
    const float* bp   = (const float*)d_in[16];
    float* out = (float*)d_out;

    float* tmp;
    cudaGetSymbolAddress((void**)&tmp, g_tmp);
    __nv_bfloat16 *xh,*xl,*eh,*el,*hh,*hl,*ench,*encl,*qh,*ql,*kh,*kl,*vh,*vl,*yh,*yl;
    __nv_bfloat16 *w1h,*w1l,*w2h,*w2l,*wqh,*wql,*wkh,*wkl,*wvh,*wvl,*wph,*wpl;
    cudaGetSymbolAddress((void**)&xh, g_xh);   cudaGetSymbolAddress((void**)&xl, g_xl);
    cudaGetSymbolAddress((void**)&eh, g_eh);   cudaGetSymbolAddress((void**)&el, g_el);
    cudaGetSymbolAddress((void**)&hh, g_hh);   cudaGetSymbolAddress((void**)&hl, g_hl);
    cudaGetSymbolAddress((void**)&ench, g_ench); cudaGetSymbolAddress((void**)&encl, g_encl);
    cudaGetSymbolAddress((void**)&qh, g_qh);   cudaGetSymbolAddress((void**)&ql, g_ql);
    cudaGetSymbolAddress((void**)&kh, g_kh);   cudaGetSymbolAddress((void**)&kl, g_kl);
    cudaGetSymbolAddress((void**)&vh, g_vh);   cudaGetSymbolAddress((void**)&vl, g_vl);
    cudaGetSymbolAddress((void**)&yh, g_yh);   cudaGetSymbolAddress((void**)&yl, g_yl);
    cudaGetSymbolAddress((void**)&w1h, g_w1h); cudaGetSymbolAddress((void**)&w1l, g_w1l);
    cudaGetSymbolAddress((void**)&w2h, g_w2h); cudaGetSymbolAddress((void**)&w2l, g_w2l);
    cudaGetSymbolAddress((void**)&wqh, g_wqh); cudaGetSymbolAddress((void**)&wql, g_wql);
    cudaGetSymbolAddress((void**)&wkh, g_wkh); cudaGetSymbolAddress((void**)&wkl, g_wkl);
    cudaGetSymbolAddress((void**)&wvh, g_wvh); cudaGetSymbolAddress((void**)&wvl, g_wvl);
    cudaGetSymbolAddress((void**)&wph, g_wph); cudaGetSymbolAddress((void**)&wpl, g_wpl);

    cudaFuncSetAttribute(gemm_cp, cudaFuncAttributeMaxDynamicSharedMemorySize, G_SMEM);
    cudaFuncSetAttribute(attn_tc, cudaFuncAttributeMaxDynamicSharedMemorySize, A_SMEM);

    cudaStream_t s1 = g_res.s1, s2 = g_res.s2;
    const size_t EHC = (size_t)EH * C_;   // encoder half offset (C cols)
    const size_t EHE = (size_t)EH * E_;   // encoder half offset (E cols)
    const size_t MHC = (size_t)MH * C_;   // decoder half offset

    // ---- fork ----
    cudaEventRecord(g_res.eS, 0);
    cudaStreamWaitEvent(s1, g_res.eS, 0);
    cudaStreamWaitEvent(s2, g_res.eS, 0);

    // s1: decoder Q chain (batch halves), later pprojA
    split_act<<<MQ * C_ / 1024, 256, 0, s1>>>(x, xh, xl);
    transpose_split<<<dim3(C_ / 32, C_ / 32), 256, 0, s1>>>(Wq, wqh, wql, C_, C_);
    gemm_cp<<<dim3(C_ / 128, MH / 128), 256, G_SMEM, s1>>>(
        xh, xl, wqh, wql, bq, nullptr, qh, ql, MH, C_, C_, 0, 0.1803368801111f);
    cudaEventRecord(g_res.eQA, s1);
    gemm_cp<<<dim3(C_ / 128, MH / 128), 256, G_SMEM, s1>>>(
        xh + MHC, xl + MHC, wqh, wql, bq, nullptr,
        qh + MHC, ql + MHC, MH, C_, C_, 0, 0.1803368801111f);
    cudaEventRecord(g_res.eQB, s1);

    // main: encoder half A chain
    split_act<<<ME * E_ / 1024, 256>>>(eemb, eh, el);
    transpose_split<<<dim3(C_ / 32, E_ / 32), 256>>>(W1, w1h, w1l, E_, C_);
    transpose_split<<<dim3(C_ / 32, C_ / 32), 256>>>(W2, w2h, w2l, C_, C_);
    cudaEventRecord(g_res.eT12, 0);
    gemm_cp<<<dim3(C_ / 128, EH / 128), 256, G_SMEM>>>(
        eh, el, w1h, w1l, b1, nullptr, hh, hl, EH, C_, E_, 1, 1.f);
    gemm_cp<<<dim3(C_ / 128, EH / 128), 256, G_SMEM>>>(
        hh, hl, w2h, w2l, b2, tmp, nullptr, nullptr, EH, C_, C_, 0, 1.f);
    ln_split<<<EH, 256>>>(tmp, lng, lnb, ench, encl);

    // s2: K/V/P transposes, then encoder half B chain + its K/V projections
    transpose_split<<<dim3(C_ / 32, C_ / 32), 256, 0, s2>>>(Wk, wkh, wkl, C_, C_);
    transpose_split<<<dim3(C_ / 32, C_ / 32), 256, 0, s2>>>(Wv, wvh, wvl, C_, C_);
    transpose_split<<<dim3(C_ / 32, C_ / 32), 256, 0, s2>>>(Wp, wph, wpl, C_, C_);
    cudaEventRecord(g_res.eW, s2);
    cudaStreamWaitEvent(s2, g_res.eT12, 0);
    gemm_cp<<<dim3(C_ / 128, EH / 128), 256, G_SMEM, s2>>>(
        eh + EHE, el + EHE, w1h, w1l, b1, nullptr, hh + EHC, hl + EHC, EH, C_, E_, 1, 1.f);
    gemm_cp<<<dim3(C_ / 128, EH / 128), 256, G_SMEM, s2>>>(
        hh + EHC, hl + EHC, w2h, w2l, b2, tmp + EHC, nullptr, nullptr, EH, C_, C_, 0, 1.f);
    ln_split<<<EH, 256, 0, s2>>>(tmp + EHC, lng, lnb, ench + EHC, encl + EHC);
    gemm_cp<<<dim3(C_ / 128, EH / 128), 256, G_SMEM, s2>>>(
        ench + EHC, encl + EHC, wkh, wkl, bk, nullptr, kh + EHC, kl + EHC, EH, C_, C_, 0, 1.f);
    gemm_cp<<<dim3(C_ / 128, EH / 128), 256, G_SMEM, s2>>>(
        ench + EHC, encl + EHC, wvh, wvl, bv, nullptr, vh + EHC, vl + EHC, EH, C_, C_, 0, 1.f);
    cudaEventRecord(g_res.eKVB, s2);

    // main: K/V projections for half A (needs Wk/Wv), then attention half A
    cudaStreamWaitEvent(0, g_res.eW, 0);
    gemm_cp<<<dim3(C_ / 128, EH / 128), 256, G_SMEM>>>(
        ench, encl, wkh, wkl, bk, nullptr, kh, kl, EH, C_, C_, 0, 1.f);
    gemm_cp<<<dim3(C_ / 128, EH / 128), 256, G_SMEM>>>(
        ench, encl, wvh, wvl, bv, nullptr, vh, vl, EH, C_, C_, 0, 1.f);
    cudaStreamWaitEvent(0, g_res.eQA, 0);
    attn_tc<<<dim3(T_ / 128, 16, 2), 256, A_SMEM>>>(
        qh, ql, kh, kl, vh, vl, emsk, yh, yl, 0);
    cudaEventRecord(g_res.eAA, 0);

    // s1: output projection half A overlaps attention half B
    cudaStreamWaitEvent(s1, g_res.eAA, 0);
    gemm_cp<<<dim3(C_ / 128, MH / 128), 256, G_SMEM, s1>>>(
        yh, yl, wph, wpl, bp, out, nullptr, nullptr, MH, C_, C_, 0, 1.f);
    cudaEventRecord(g_res.ePA, s1);

    // main: attention half B, output projection half B, join
    cudaStreamWaitEvent(0, g_res.eQB, 0);
    cudaStreamWaitEvent(0, g_res.eKVB, 0);
    attn_tc<<<dim3(T_ / 128, 16, 2), 256, A_SMEM>>>(
        qh, ql, kh, kl, vh, vl, emsk, yh, yl, 2);
    gemm_cp<<<dim3(C_ / 128, MH / 128), 256, G_SMEM>>>(
        yh + MHC, yl + MHC, wph, wpl, bp,
        out + MHC, nullptr, nullptr, MH, C_, C_, 0, 1.f);
    cudaStreamWaitEvent(0, g_res.ePA, 0);
}